// round 1
// baseline (speedup 1.0000x reference)
#include <cuda_runtime.h>

#define B_ 4
#define T_ 2048
#define C_ 1024
#define H_ 16
#define D_ 64
#define M_ROWS (B_ * T_)   /* 8192 */
#define KDIM   C_          /* 1024 */
#define NCOL   C_          /* 1024 */

// Scratch (allocation-free rule: __device__ globals)
__device__ float g_q[B_ * H_ * T_ * D_];
__device__ float g_k[B_ * H_ * T_ * D_];
__device__ float g_v[B_ * H_ * T_ * D_];
__device__ float g_attn[B_ * T_ * C_];

// ---------------------------------------------------------------------------
// SGEMM: out = X[M,K] @ W[N,K]^T + bias[N]
// 128x128 block tile, 256 threads, 8x8 micro-tile, K-step 8.
// headsplit=1: output written to [B,H,T,D] layout (col -> h,d ; row -> b,t)
// ---------------------------------------------------------------------------
__global__ __launch_bounds__(256, 2)
void sgemm_xwT(const float* __restrict__ X, const float* __restrict__ W,
               const float* __restrict__ bias, float* __restrict__ out,
               int headsplit)
{
    __shared__ float As[8][132];   // As[k][i], pitch 132 -> conflict-free
    __shared__ float Bs[8][132];   // Bs[k][j]

    const int tid = threadIdx.x;
    const int tx = tid & 15;
    const int ty = tid >> 4;
    const int row0 = blockIdx.y * 128;
    const int col0 = blockIdx.x * 128;

    // load mapping: each thread loads one float4 of X and one of W per K-step
    const int li = tid >> 1;          // 0..127 (tile row)
    const int lk = (tid & 1) * 4;     // 0 or 4 (k offset)

    const float* Xp = X + (size_t)(row0 + li) * KDIM + lk;
    const float* Wp = W + (size_t)(col0 + li) * KDIM + lk;

    float acc[8][8];
#pragma unroll
    for (int i = 0; i < 8; i++)
#pragma unroll
        for (int j = 0; j < 8; j++) acc[i][j] = 0.0f;

    for (int k0 = 0; k0 < KDIM; k0 += 8) {
        float4 xa = *(const float4*)(Xp + k0);
        float4 wb = *(const float4*)(Wp + k0);
        As[lk + 0][li] = xa.x; As[lk + 1][li] = xa.y;
        As[lk + 2][li] = xa.z; As[lk + 3][li] = xa.w;
        Bs[lk + 0][li] = wb.x; Bs[lk + 1][li] = wb.y;
        Bs[lk + 2][li] = wb.z; Bs[lk + 3][li] = wb.w;
        __syncthreads();

#pragma unroll
        for (int k = 0; k < 8; k++) {
            float a[8], b[8];
            *(float4*)(a)     = *(const float4*)(&As[k][ty * 8]);
            *(float4*)(a + 4) = *(const float4*)(&As[k][ty * 8 + 4]);
            *(float4*)(b)     = *(const float4*)(&Bs[k][tx * 8]);
            *(float4*)(b + 4) = *(const float4*)(&Bs[k][tx * 8 + 4]);
#pragma unroll
            for (int i = 0; i < 8; i++)
#pragma unroll
                for (int j = 0; j < 8; j++)
                    acc[i][j] += a[i] * b[j];
        }
        __syncthreads();
    }

    // epilogue
#pragma unroll
    for (int i = 0; i < 8; i++) {
        const int row = row0 + ty * 8 + i;
        const int b   = row >> 11;        // row / 2048
        const int t   = row & (T_ - 1);
#pragma unroll
        for (int j = 0; j < 8; j++) {
            const int col = col0 + tx * 8 + j;
            const float v = acc[i][j] + bias[col];
            if (headsplit) {
                const int h = col >> 6;
                const int d = col & 63;
                out[(size_t)b * (H_ * T_ * D_) + (size_t)h * (T_ * D_)
                    + (size_t)t * D_ + d] = v;
            } else {
                out[(size_t)row * NCOL + col] = v;
            }
        }
    }
}

// ---------------------------------------------------------------------------
// Flash attention, fp32. One block per (b*H+h, q-tile of 64 rows).
// Br=Bc=64, 256 threads; thread (ty,tx) owns 4x4 of S (rows ty*4.., cols tx*4..)
// and 4x4 of O (rows ty*4.., d-cols tx*4..). Online softmax; row reductions via
// __shfl_xor within the 16-lane tx-group.
// ---------------------------------------------------------------------------
__global__ __launch_bounds__(256)
void flash_attn(const float* __restrict__ Q, const float* __restrict__ K,
                const float* __restrict__ V, float* __restrict__ Out)
{
    extern __shared__ float sm[];
    float* Qs = sm;                 // [64][65]
    float* Ks = sm + 64 * 65;       // [64][65]
    float* Ps = sm + 2 * 64 * 65;   // [64][65]
    float* Vs = sm + 3 * 64 * 65;   // [64][64]

    const int tid = threadIdx.x;
    const int tx = tid & 15;
    const int ty = tid >> 4;
    const int bh = blockIdx.y;      // 0..63  (b*H + h)
    const int qt = blockIdx.x;      // 0..31

    const float* Qb = Q + (size_t)bh * (T_ * D_) + (size_t)qt * 64 * D_;
    const float* Kb = K + (size_t)bh * (T_ * D_);
    const float* Vb = V + (size_t)bh * (T_ * D_);

    // Load Q tile once (4096 floats)
#pragma unroll
    for (int it = 0; it < 4; it++) {
        const int f  = tid + it * 256;
        const int r  = f >> 4;
        const int d0 = (f & 15) * 4;
        float4 v = *(const float4*)(Qb + r * D_ + d0);
        Qs[r * 65 + d0 + 0] = v.x;
        Qs[r * 65 + d0 + 1] = v.y;
        Qs[r * 65 + d0 + 2] = v.z;
        Qs[r * 65 + d0 + 3] = v.w;
    }

    const int r0 = ty * 4;
    const int c0 = tx * 4;

    float m[4], l[4], acc[4][4];
#pragma unroll
    for (int i = 0; i < 4; i++) {
        m[i] = -1e30f;
        l[i] = 0.0f;
#pragma unroll
        for (int j = 0; j < 4; j++) acc[i][j] = 0.0f;
    }

    for (int kt = 0; kt < T_ / 64; kt++) {
        __syncthreads();   // previous-tile consumers of Ks/Vs/Ps done

        const float* Kt = Kb + (size_t)kt * 64 * D_;
        const float* Vt = Vb + (size_t)kt * 64 * D_;
#pragma unroll
        for (int it = 0; it < 4; it++) {
            const int f  = tid + it * 256;
            const int r  = f >> 4;
            const int d0 = (f & 15) * 4;
            float4 kv = *(const float4*)(Kt + r * D_ + d0);
            Ks[r * 65 + d0 + 0] = kv.x;
            Ks[r * 65 + d0 + 1] = kv.y;
            Ks[r * 65 + d0 + 2] = kv.z;
            Ks[r * 65 + d0 + 3] = kv.w;
            float4 vv = *(const float4*)(Vt + r * D_ + d0);
            *(float4*)(&Vs[r * 64 + d0]) = vv;
        }
        __syncthreads();

        // ---- S = Q K^T (64x64x64) ----
        float s[4][4];
#pragma unroll
        for (int i = 0; i < 4; i++)
#pragma unroll
            for (int j = 0; j < 4; j++) s[i][j] = 0.0f;

#pragma unroll 8
        for (int k = 0; k < 64; k++) {
            float a[4], bb[4];
#pragma unroll
            for (int i = 0; i < 4; i++) a[i]  = Qs[(r0 + i) * 65 + k];
#pragma unroll
            for (int j = 0; j < 4; j++) bb[j] = Ks[(c0 + j) * 65 + k];
#pragma unroll
            for (int i = 0; i < 4; i++)
#pragma unroll
                for (int j = 0; j < 4; j++)
                    s[i][j] += a[i] * bb[j];
        }

        // ---- online softmax ----
#pragma unroll
        for (int i = 0; i < 4; i++)
#pragma unroll
            for (int j = 0; j < 4; j++)
                s[i][j] *= 0.125f;   // 1/sqrt(64)

#pragma unroll
        for (int i = 0; i < 4; i++) {
            float tm = fmaxf(fmaxf(s[i][0], s[i][1]), fmaxf(s[i][2], s[i][3]));
#pragma unroll
            for (int off = 8; off >= 1; off >>= 1)
                tm = fmaxf(tm, __shfl_xor_sync(0xffffffffu, tm, off));
            const float mnew  = fmaxf(m[i], tm);
            const float alpha = __expf(m[i] - mnew);

            float rowsum = 0.0f;
#pragma unroll
            for (int j = 0; j < 4; j++) {
                const float p = __expf(s[i][j] - mnew);
                s[i][j] = p;
                rowsum += p;
            }
#pragma unroll
            for (int off = 8; off >= 1; off >>= 1)
                rowsum += __shfl_xor_sync(0xffffffffu, rowsum, off);

            l[i] = l[i] * alpha + rowsum;
            m[i] = mnew;
#pragma unroll
            for (int j = 0; j < 4; j++) acc[i][j] *= alpha;
        }

        // stage P
#pragma unroll
        for (int i = 0; i < 4; i++)
#pragma unroll
            for (int j = 0; j < 4; j++)
                Ps[(r0 + i) * 65 + (c0 + j)] = s[i][j];
        __syncthreads();

        // ---- O += P V (64x64x64) ----
#pragma unroll 8
        for (int c = 0; c < 64; c++) {
            float a[4];
#pragma unroll
            for (int i = 0; i < 4; i++) a[i] = Ps[(r0 + i) * 65 + c];
            const float4 b4 = *(const float4*)(&Vs[c * 64 + c0]);
#pragma unroll
            for (int i = 0; i < 4; i++) {
                acc[i][0] += a[i] * b4.x;
                acc[i][1] += a[i] * b4.y;
                acc[i][2] += a[i] * b4.z;
                acc[i][3] += a[i] * b4.w;
            }
        }
    }

    // ---- write O / l  into [B,T,C] attn buffer ----
    const int b = bh >> 4;
    const int h = bh & 15;
#pragma unroll
    for (int i = 0; i < 4; i++) {
        const int t = qt * 64 + r0 + i;
        const float inv = 1.0f / l[i];
        float4 o;
        o.x = acc[i][0] * inv;
        o.y = acc[i][1] * inv;
        o.z = acc[i][2] * inv;
        o.w = acc[i][3] * inv;
        *(float4*)(&Out[(size_t)(b * T_ + t) * C_ + h * 64 + c0]) = o;
    }
}

// ---------------------------------------------------------------------------
extern "C" void kernel_launch(void* const* d_in, const int* in_sizes, int n_in,
                              void* d_out, int out_size)
{
    const float* querys = (const float*)d_in[0];
    const float* keys   = (const float*)d_in[1];
    const float* values = (const float*)d_in[2];
    const float* Wq = (const float*)d_in[3];
    const float* bq = (const float*)d_in[4];
    const float* Wk = (const float*)d_in[5];
    const float* bk = (const float*)d_in[6];
    const float* Wv = (const float*)d_in[7];
    const float* bv = (const float*)d_in[8];
    const float* Wo = (const float*)d_in[9];
    const float* bo = (const float*)d_in[10];

    float *qp, *kp, *vp, *ap;
    cudaGetSymbolAddress((void**)&qp, g_q);
    cudaGetSymbolAddress((void**)&kp, g_k);
    cudaGetSymbolAddress((void**)&vp, g_v);
    cudaGetSymbolAddress((void**)&ap, g_attn);

    const size_t smem = (size_t)(3 * 64 * 65 + 64 * 64) * sizeof(float); // 66304
    cudaFuncSetAttribute(flash_attn, cudaFuncAttributeMaxDynamicSharedMemorySize,
                         (int)smem);

    const dim3 gg(NCOL / 128, M_ROWS / 128);   // (8, 64)
    sgemm_xwT<<<gg, 256>>>(querys, Wq, bq, qp, 1);
    sgemm_xwT<<<gg, 256>>>(keys,   Wk, bk, kp, 1);
    sgemm_xwT<<<gg, 256>>>(values, Wv, bv, vp, 1);

    flash_attn<<<dim3(T_ / 64, B_ * H_), 256, smem>>>(qp, kp, vp, ap);

    sgemm_xwT<<<gg, 256>>>(ap, Wo, bo, (float*)d_out, 0);
}

// round 4
// speedup vs baseline: 1.0136x; 1.0136x over previous
#include <cuda_runtime.h>
#include <cstdint>

#define B_ 4
#define T_ 2048
#define C_ 1024
#define H_ 16
#define D_ 64
#define M_ROWS (B_ * T_)   /* 8192 */
#define KDIM   C_          /* 1024 */
#define NCOL   C_          /* 1024 */

// Scratch (allocation-free rule: __device__ globals)
__device__ float g_q[B_ * H_ * T_ * D_];
__device__ float g_k[B_ * H_ * T_ * D_];
__device__ float g_v[B_ * H_ * T_ * D_];
__device__ float g_attn[B_ * T_ * C_];

// ===========================================================================
// mma.sync tf32 helpers. NOTE: tf32 A/B operands must be .b32 regs ("r"),
// accumulators are .f32 ("f") — R3's "f" on A/B was the ptxas mismatch.
// ===========================================================================
__device__ __forceinline__ uint32_t tf32_rna_bits(float x) {
    uint32_t r;
    asm("cvt.rna.tf32.f32 %0, %1;" : "=r"(r) : "f"(x));
    return r;
}

// D(16x8,f32) += A(16x8,tf32) * B(8x8,tf32)
__device__ __forceinline__ void mma_tf32(float* d, const uint32_t* a,
                                         const uint32_t* b) {
    asm volatile(
        "mma.sync.aligned.m16n8k8.row.col.f32.tf32.tf32.f32 "
        "{%0,%1,%2,%3}, {%4,%5,%6,%7}, {%8,%9}, {%0,%1,%2,%3};"
        : "+f"(d[0]), "+f"(d[1]), "+f"(d[2]), "+f"(d[3])
        : "r"(a[0]), "r"(a[1]), "r"(a[2]), "r"(a[3]),
          "r"(b[0]), "r"(b[1]));
}

// ===========================================================================
// 3xTF32 GEMM: out = X[M,K] @ W[N,K]^T + bias[N]
// CTA 128x128, 256 threads (8 warps as 2m x 4n), warp tile 64x32.
// K-chunk 16, 2-stage double buffer, fragment-packed smem layout:
//   A atom (16m x 8k) = 32 lanes * 4 u32 (LDS.128 per frag)
//   B atom ( 8k x 8n) = 32 lanes * 2 u32 (LDS.64 per frag)
// headsplit=1: output written to [B,H,T,D] layout.
// ===========================================================================
#define KC 16
#define NCHUNK (KDIM / KC)   /* 64 */
// stage layout (bytes): AHI 8K | ALO 8K | BHI 8K | BLO 8K  = 32KB; 2 stages
#define ST_AHI 0
#define ST_ALO 8192
#define ST_BHI 16384
#define ST_BLO 24576
#define STG_B  32768
#define GEMM_SMEM (2 * STG_B)

__global__ __launch_bounds__(256, 1)
void gemm_mma(const float* __restrict__ X, const float* __restrict__ W,
              const float* __restrict__ bias, float* __restrict__ out,
              int headsplit)
{
    extern __shared__ __align__(16) char smem[];

    const int tid  = threadIdx.x;
    const int wid  = tid >> 5;
    const int lane = tid & 31;
    const int wm   = wid >> 2;        // 0..1
    const int wn   = wid & 3;         // 0..3
    const int col0 = blockIdx.x * 128;
    const int row0 = blockIdx.y * 128;

    const float* Xp = X + (size_t)row0 * KDIM;
    const float* Wp = W + (size_t)col0 * KDIM;

    // producer mapping: float4 index v = tid + it*256 (it=0,1) covers 512
    // float4 = 128 rows x 16 k.  r = v>>2, kq = (v&3)*4.
    float4 ra[2], rb[2];

    auto ldg_chunk = [&](int j) {
#pragma unroll
        for (int it = 0; it < 2; it++) {
            const int v  = tid + it * 256;
            const int r  = v >> 2;
            const int kq = (v & 3) * 4;
            ra[it] = *(const float4*)(Xp + (size_t)r * KDIM + j * KC + kq);
            rb[it] = *(const float4*)(Wp + (size_t)r * KDIM + j * KC + kq);
        }
    };

    auto sts_chunk = [&](int stg) {
        char* sbase = smem + stg * STG_B;
#pragma unroll
        for (int it = 0; it < 2; it++) {
            const int v  = tid + it * 256;
            const int r  = v >> 2;
            const int kq = (v & 3) * 4;
            const float xv[4] = {ra[it].x, ra[it].y, ra[it].z, ra[it].w};
            const float wv[4] = {rb[it].x, rb[it].y, rb[it].z, rb[it].w};
            // A: atom (mi = r>>4, ki = kq>>3); rr=r&15
            {
                const int mi = r >> 4, ki = kq >> 3;
                const int rr = r & 15;
                const int reg = (rr >> 3) | (((kq >> 2) & 1) << 1);
                char* ab = sbase + (mi * 2 + ki) * 512 + ((rr & 7) << 2) * 16 + reg * 4;
#pragma unroll
                for (int q = 0; q < 4; q++) {
                    const uint32_t hi = tf32_rna_bits(xv[q]);
                    const uint32_t lo = tf32_rna_bits(xv[q] - __uint_as_float(hi));
                    *(uint32_t*)(ab + ST_AHI + q * 16) = hi;
                    *(uint32_t*)(ab + ST_ALO + q * 16) = lo;
                }
            }
            // B: atom (ni = r>>3, ki = kq>>3); nn=r&7
            {
                const int ni = r >> 3, ki = kq >> 3;
                const int nn = r & 7;
                const int reg = (kq >> 2) & 1;
                char* bb = sbase + (ni * 2 + ki) * 256 + (nn << 2) * 8 + reg * 4;
#pragma unroll
                for (int q = 0; q < 4; q++) {
                    const uint32_t hi = tf32_rna_bits(wv[q]);
                    const uint32_t lo = tf32_rna_bits(wv[q] - __uint_as_float(hi));
                    *(uint32_t*)(bb + ST_BHI + q * 8) = hi;
                    *(uint32_t*)(bb + ST_BLO + q * 8) = lo;
                }
            }
        }
    };

    float acc[4][4][4];
#pragma unroll
    for (int i = 0; i < 4; i++)
#pragma unroll
        for (int j = 0; j < 4; j++)
#pragma unroll
            for (int q = 0; q < 4; q++) acc[i][j][q] = 0.0f;

    // prologue
    ldg_chunk(0);
    sts_chunk(0);
    ldg_chunk(1);

    for (int j = 0; j < NCHUNK; ++j) {
        const int s = j & 1;
        if (j + 1 < NCHUNK) sts_chunk(s ^ 1);
        __syncthreads();
        if (j + 2 < NCHUNK) ldg_chunk(j + 2);

        const char* sbase = smem + s * STG_B;
#pragma unroll
        for (int ki = 0; ki < 2; ki++) {
            uint32_t ah[4][4], al[4][4], bh[4][2], bl[4][2];
#pragma unroll
            for (int mi = 0; mi < 4; mi++) {
                const char* ab = sbase + ((wm * 4 + mi) * 2 + ki) * 512 + lane * 16;
                *(uint4*)ah[mi] = *(const uint4*)(ab + ST_AHI);
                *(uint4*)al[mi] = *(const uint4*)(ab + ST_ALO);
            }
#pragma unroll
            for (int ni = 0; ni < 4; ni++) {
                const char* bb = sbase + ((wn * 4 + ni) * 2 + ki) * 256 + lane * 8;
                *(uint2*)bh[ni] = *(const uint2*)(bb + ST_BHI);
                *(uint2*)bl[ni] = *(const uint2*)(bb + ST_BLO);
            }
#pragma unroll
            for (int mi = 0; mi < 4; mi++)
#pragma unroll
                for (int ni = 0; ni < 4; ni++) {
                    mma_tf32(acc[mi][ni], ah[mi], bh[ni]);
                    mma_tf32(acc[mi][ni], ah[mi], bl[ni]);
                    mma_tf32(acc[mi][ni], al[mi], bh[ni]);
                }
        }
        __syncthreads();
    }

    // epilogue: frag (mi,ni): rows row0+wm*64+mi*16+(lane>>2)[+8],
    // cols col0+wn*32+ni*8+(lane&3)*2 (+1)
#pragma unroll
    for (int ni = 0; ni < 4; ni++) {
        const int col = col0 + wn * 32 + ni * 8 + (lane & 3) * 2;
        const float2 bv = *(const float2*)(bias + col);
#pragma unroll
        for (int mi = 0; mi < 4; mi++) {
#pragma unroll
            for (int h = 0; h < 2; h++) {   // h=0 -> rows +0, h=1 -> rows +8
                const int row = row0 + wm * 64 + mi * 16 + (lane >> 2) + h * 8;
                float2 o;
                o.x = acc[mi][ni][h * 2 + 0] + bv.x;
                o.y = acc[mi][ni][h * 2 + 1] + bv.y;
                float* dst;
                if (headsplit) {
                    const int b = row >> 11;
                    const int t = row & (T_ - 1);
                    const int hh = col >> 6;
                    const int dd = col & 63;
                    dst = out + (size_t)b * (H_ * T_ * D_) + (size_t)hh * (T_ * D_)
                        + (size_t)t * D_ + dd;
                } else {
                    dst = out + (size_t)row * NCOL + col;
                }
                *(float2*)dst = o;
            }
        }
    }
}

// ---------------------------------------------------------------------------
// Flash attention, fp32 (unchanged — proven correct/fast at fp32 roofline)
// ---------------------------------------------------------------------------
__global__ __launch_bounds__(256)
void flash_attn(const float* __restrict__ Q, const float* __restrict__ K,
                const float* __restrict__ V, float* __restrict__ Out)
{
    extern __shared__ float sm[];
    float* Qs = sm;
    float* Ks = sm + 64 * 65;
    float* Ps = sm + 2 * 64 * 65;
    float* Vs = sm + 3 * 64 * 65;

    const int tid = threadIdx.x;
    const int tx = tid & 15;
    const int ty = tid >> 4;
    const int bh = blockIdx.y;
    const int qt = blockIdx.x;

    const float* Qb = Q + (size_t)bh * (T_ * D_) + (size_t)qt * 64 * D_;
    const float* Kb = K + (size_t)bh * (T_ * D_);
    const float* Vb = V + (size_t)bh * (T_ * D_);

#pragma unroll
    for (int it = 0; it < 4; it++) {
        const int f  = tid + it * 256;
        const int r  = f >> 4;
        const int d0 = (f & 15) * 4;
        float4 v = *(const float4*)(Qb + r * D_ + d0);
        Qs[r * 65 + d0 + 0] = v.x;
        Qs[r * 65 + d0 + 1] = v.y;
        Qs[r * 65 + d0 + 2] = v.z;
        Qs[r * 65 + d0 + 3] = v.w;
    }

    const int r0 = ty * 4;
    const int c0 = tx * 4;

    float m[4], l[4], acc[4][4];
#pragma unroll
    for (int i = 0; i < 4; i++) {
        m[i] = -1e30f;
        l[i] = 0.0f;
#pragma unroll
        for (int j = 0; j < 4; j++) acc[i][j] = 0.0f;
    }

    for (int kt = 0; kt < T_ / 64; kt++) {
        __syncthreads();

        const float* Kt = Kb + (size_t)kt * 64 * D_;
        const float* Vt = Vb + (size_t)kt * 64 * D_;
#pragma unroll
        for (int it = 0; it < 4; it++) {
            const int f  = tid + it * 256;
            const int r  = f >> 4;
            const int d0 = (f & 15) * 4;
            float4 kv = *(const float4*)(Kt + r * D_ + d0);
            Ks[r * 65 + d0 + 0] = kv.x;
            Ks[r * 65 + d0 + 1] = kv.y;
            Ks[r * 65 + d0 + 2] = kv.z;
            Ks[r * 65 + d0 + 3] = kv.w;
            float4 vv = *(const float4*)(Vt + r * D_ + d0);
            *(float4*)(&Vs[r * 64 + d0]) = vv;
        }
        __syncthreads();

        float s[4][4];
#pragma unroll
        for (int i = 0; i < 4; i++)
#pragma unroll
            for (int j = 0; j < 4; j++) s[i][j] = 0.0f;

#pragma unroll 8
        for (int k = 0; k < 64; k++) {
            float a[4], bb[4];
#pragma unroll
            for (int i = 0; i < 4; i++) a[i]  = Qs[(r0 + i) * 65 + k];
#pragma unroll
            for (int j = 0; j < 4; j++) bb[j] = Ks[(c0 + j) * 65 + k];
#pragma unroll
            for (int i = 0; i < 4; i++)
#pragma unroll
                for (int j = 0; j < 4; j++)
                    s[i][j] += a[i] * bb[j];
        }

#pragma unroll
        for (int i = 0; i < 4; i++)
#pragma unroll
            for (int j = 0; j < 4; j++)
                s[i][j] *= 0.125f;

#pragma unroll
        for (int i = 0; i < 4; i++) {
            float tm = fmaxf(fmaxf(s[i][0], s[i][1]), fmaxf(s[i][2], s[i][3]));
#pragma unroll
            for (int off = 8; off >= 1; off >>= 1)
                tm = fmaxf(tm, __shfl_xor_sync(0xffffffffu, tm, off));
            const float mnew  = fmaxf(m[i], tm);
            const float alpha = __expf(m[i] - mnew);

            float rowsum = 0.0f;
#pragma unroll
            for (int j = 0; j < 4; j++) {
                const float p = __expf(s[i][j] - mnew);
                s[i][j] = p;
                rowsum += p;
            }
#pragma unroll
            for (int off = 8; off >= 1; off >>= 1)
                rowsum += __shfl_xor_sync(0xffffffffu, rowsum, off);

            l[i] = l[i] * alpha + rowsum;
            m[i] = mnew;
#pragma unroll
            for (int j = 0; j < 4; j++) acc[i][j] *= alpha;
        }

#pragma unroll
        for (int i = 0; i < 4; i++)
#pragma unroll
            for (int j = 0; j < 4; j++)
                Ps[(r0 + i) * 65 + (c0 + j)] = s[i][j];
        __syncthreads();

#pragma unroll 8
        for (int c = 0; c < 64; c++) {
            float a[4];
#pragma unroll
            for (int i = 0; i < 4; i++) a[i] = Ps[(r0 + i) * 65 + c];
            const float4 b4 = *(const float4*)(&Vs[c * 64 + c0]);
#pragma unroll
            for (int i = 0; i < 4; i++) {
                acc[i][0] += a[i] * b4.x;
                acc[i][1] += a[i] * b4.y;
                acc[i][2] += a[i] * b4.z;
                acc[i][3] += a[i] * b4.w;
            }
        }
    }

    const int b = bh >> 4;
    const int h = bh & 15;
#pragma unroll
    for (int i = 0; i < 4; i++) {
        const int t = qt * 64 + r0 + i;
        const float inv = 1.0f / l[i];
        float4 o;
        o.x = acc[i][0] * inv;
        o.y = acc[i][1] * inv;
        o.z = acc[i][2] * inv;
        o.w = acc[i][3] * inv;
        *(float4*)(&Out[(size_t)(b * T_ + t) * C_ + h * 64 + c0]) = o;
    }
}

// ---------------------------------------------------------------------------
extern "C" void kernel_launch(void* const* d_in, const int* in_sizes, int n_in,
                              void* d_out, int out_size)
{
    const float* querys = (const float*)d_in[0];
    const float* keys   = (const float*)d_in[1];
    const float* values = (const float*)d_in[2];
    const float* Wq = (const float*)d_in[3];
    const float* bq = (const float*)d_in[4];
    const float* Wk = (const float*)d_in[5];
    const float* bk = (const float*)d_in[6];
    const float* Wv = (const float*)d_in[7];
    const float* bv = (const float*)d_in[8];
    const float* Wo = (const float*)d_in[9];
    const float* bo = (const float*)d_in[10];

    float *qp, *kp, *vp, *ap;
    cudaGetSymbolAddress((void**)&qp, g_q);
    cudaGetSymbolAddress((void**)&kp, g_k);
    cudaGetSymbolAddress((void**)&vp, g_v);
    cudaGetSymbolAddress((void**)&ap, g_attn);

    cudaFuncSetAttribute(gemm_mma, cudaFuncAttributeMaxDynamicSharedMemorySize,
                         GEMM_SMEM);
    const size_t fsmem = (size_t)(3 * 64 * 65 + 64 * 64) * sizeof(float);
    cudaFuncSetAttribute(flash_attn, cudaFuncAttributeMaxDynamicSharedMemorySize,
                         (int)fsmem);

    const dim3 gg(NCOL / 128, M_ROWS / 128);   // (8, 64)

    gemm_mma<<<gg, 256, GEMM_SMEM>>>(querys, Wq, bq, qp, 1);
    gemm_mma<<<gg, 256, GEMM_SMEM>>>(keys,   Wk, bk, kp, 1);
    gemm_mma<<<gg, 256, GEMM_SMEM>>>(values, Wv, bv, vp, 1);

    flash_attn<<<dim3(T_ / 64, B_ * H_), 256, fsmem>>>(qp, kp, vp, ap);

    gemm_mma<<<gg, 256, GEMM_SMEM>>>(ap, Wo, bo, (float*)d_out, 0);
}

// round 7
// speedup vs baseline: 1.2175x; 1.2011x over previous
#include <cuda_runtime.h>
#include <cstdint>

#define B_ 4
#define T_ 2048
#define C_ 1024
#define H_ 16
#define D_ 64
#define M_ROWS (B_ * T_)   /* 8192 */
#define KDIM   C_          /* 1024 */
#define NCOL   C_          /* 1024 */

// Scratch (allocation-free rule: __device__ globals)
__device__ float g_q[B_ * H_ * T_ * D_];
__device__ float g_k[B_ * H_ * T_ * D_];
__device__ float g_v[B_ * H_ * T_ * D_];
__device__ float g_attn[B_ * T_ * C_];

// ===========================================================================
// mma.sync tf32 helpers (A/B are .b32 regs, accum .f32)
// ===========================================================================
__device__ __forceinline__ uint32_t tf32_rna_bits(float x) {
    uint32_t r;
    asm("cvt.rna.tf32.f32 %0, %1;" : "=r"(r) : "f"(x));
    return r;
}

// D(16x8,f32) += A(16x8,tf32) * B(8x8,tf32)
__device__ __forceinline__ void mma_tf32(float* d, const uint32_t* a,
                                         const uint32_t* b) {
    asm volatile(
        "mma.sync.aligned.m16n8k8.row.col.f32.tf32.tf32.f32 "
        "{%0,%1,%2,%3}, {%4,%5,%6,%7}, {%8,%9}, {%0,%1,%2,%3};"
        : "+f"(d[0]), "+f"(d[1]), "+f"(d[2]), "+f"(d[3])
        : "r"(a[0]), "r"(a[1]), "r"(a[2]), "r"(a[3]),
          "r"(b[0]), "r"(b[1]));
}

// ===========================================================================
// 3xTF32 GEMM (as R4, but min 2 CTAs/SM to overlap producer with barriers)
// ===========================================================================
#define KC 16
#define NCHUNK (KDIM / KC)   /* 64 */
#define ST_AHI 0
#define ST_ALO 8192
#define ST_BHI 16384
#define ST_BLO 24576
#define STG_B  32768
#define GEMM_SMEM (2 * STG_B)

__global__ __launch_bounds__(256, 2)
void gemm_mma(const float* __restrict__ X, const float* __restrict__ W,
              const float* __restrict__ bias, float* __restrict__ out,
              int headsplit)
{
    extern __shared__ __align__(16) char smem[];

    const int tid  = threadIdx.x;
    const int wid  = tid >> 5;
    const int lane = tid & 31;
    const int wm   = wid >> 2;
    const int wn   = wid & 3;
    const int col0 = blockIdx.x * 128;
    const int row0 = blockIdx.y * 128;

    const float* Xp = X + (size_t)row0 * KDIM;
    const float* Wp = W + (size_t)col0 * KDIM;

    float4 ra[2], rb[2];

    auto ldg_chunk = [&](int j) {
#pragma unroll
        for (int it = 0; it < 2; it++) {
            const int v  = tid + it * 256;
            const int r  = v >> 2;
            const int kq = (v & 3) * 4;
            ra[it] = *(const float4*)(Xp + (size_t)r * KDIM + j * KC + kq);
            rb[it] = *(const float4*)(Wp + (size_t)r * KDIM + j * KC + kq);
        }
    };

    auto sts_chunk = [&](int stg) {
        char* sbase = smem + stg * STG_B;
#pragma unroll
        for (int it = 0; it < 2; it++) {
            const int v  = tid + it * 256;
            const int r  = v >> 2;
            const int kq = (v & 3) * 4;
            const float xv[4] = {ra[it].x, ra[it].y, ra[it].z, ra[it].w};
            const float wv[4] = {rb[it].x, rb[it].y, rb[it].z, rb[it].w};
            {
                const int mi = r >> 4, ki = kq >> 3;
                const int rr = r & 15;
                const int reg = (rr >> 3) | (((kq >> 2) & 1) << 1);
                char* ab = sbase + (mi * 2 + ki) * 512 + ((rr & 7) << 2) * 16 + reg * 4;
#pragma unroll
                for (int q = 0; q < 4; q++) {
                    const uint32_t hi = tf32_rna_bits(xv[q]);
                    const uint32_t lo = tf32_rna_bits(xv[q] - __uint_as_float(hi));
                    *(uint32_t*)(ab + ST_AHI + q * 16) = hi;
                    *(uint32_t*)(ab + ST_ALO + q * 16) = lo;
                }
            }
            {
                const int ni = r >> 3, ki = kq >> 3;
                const int nn = r & 7;
                const int reg = (kq >> 2) & 1;
                char* bb = sbase + (ni * 2 + ki) * 256 + (nn << 2) * 8 + reg * 4;
#pragma unroll
                for (int q = 0; q < 4; q++) {
                    const uint32_t hi = tf32_rna_bits(wv[q]);
                    const uint32_t lo = tf32_rna_bits(wv[q] - __uint_as_float(hi));
                    *(uint32_t*)(bb + ST_BHI + q * 8) = hi;
                    *(uint32_t*)(bb + ST_BLO + q * 8) = lo;
                }
            }
        }
    };

    float acc[4][4][4];
#pragma unroll
    for (int i = 0; i < 4; i++)
#pragma unroll
        for (int j = 0; j < 4; j++)
#pragma unroll
            for (int q = 0; q < 4; q++) acc[i][j][q] = 0.0f;

    ldg_chunk(0);
    sts_chunk(0);
    ldg_chunk(1);

    for (int j = 0; j < NCHUNK; ++j) {
        const int s = j & 1;
        if (j + 1 < NCHUNK) sts_chunk(s ^ 1);
        __syncthreads();
        if (j + 2 < NCHUNK) ldg_chunk(j + 2);

        const char* sbase = smem + s * STG_B;
#pragma unroll
        for (int ki = 0; ki < 2; ki++) {
            uint32_t ah[4][4], al[4][4], bh[4][2], bl[4][2];
#pragma unroll
            for (int mi = 0; mi < 4; mi++) {
                const char* ab = sbase + ((wm * 4 + mi) * 2 + ki) * 512 + lane * 16;
                *(uint4*)ah[mi] = *(const uint4*)(ab + ST_AHI);
                *(uint4*)al[mi] = *(const uint4*)(ab + ST_ALO);
            }
#pragma unroll
            for (int ni = 0; ni < 4; ni++) {
                const char* bb = sbase + ((wn * 4 + ni) * 2 + ki) * 256 + lane * 8;
                *(uint2*)bh[ni] = *(const uint2*)(bb + ST_BHI);
                *(uint2*)bl[ni] = *(const uint2*)(bb + ST_BLO);
            }
#pragma unroll
            for (int mi = 0; mi < 4; mi++)
#pragma unroll
                for (int ni = 0; ni < 4; ni++) {
                    mma_tf32(acc[mi][ni], ah[mi], bh[ni]);
                    mma_tf32(acc[mi][ni], ah[mi], bl[ni]);
                    mma_tf32(acc[mi][ni], al[mi], bh[ni]);
                }
        }
        __syncthreads();
    }

#pragma unroll
    for (int ni = 0; ni < 4; ni++) {
        const int col = col0 + wn * 32 + ni * 8 + (lane & 3) * 2;
        const float2 bv = *(const float2*)(bias + col);
#pragma unroll
        for (int mi = 0; mi < 4; mi++) {
#pragma unroll
            for (int h = 0; h < 2; h++) {
                const int row = row0 + wm * 64 + mi * 16 + (lane >> 2) + h * 8;
                float2 o;
                o.x = acc[mi][ni][h * 2 + 0] + bv.x;
                o.y = acc[mi][ni][h * 2 + 1] + bv.y;
                float* dst;
                if (headsplit) {
                    const int b = row >> 11;
                    const int t = row & (T_ - 1);
                    const int hh = col >> 6;
                    const int dd = col & 63;
                    dst = out + (size_t)b * (H_ * T_ * D_) + (size_t)hh * (T_ * D_)
                        + (size_t)t * D_ + dd;
                } else {
                    dst = out + (size_t)row * NCOL + col;
                }
                *(float2*)dst = o;
            }
        }
    }
}

// ===========================================================================
// Flash attention on mma.sync tf32.
// Br=128 (8 warps x 16 rows), Bc=64. Q cached in registers as hi/lo A-frags.
// K tile frag-packed hi/lo in smem, V tile frag-packed single tf32.
// S = QK^T: 3xTF32. Softmax fp32 in registers. P: accum->A-operand layout via
// quad shuffles, split hi/lo; O += P V: 2 passes (V single tf32).
// ===========================================================================
#define FA_BC 64
#define SM_KH 0
#define SM_KL 16384
#define SM_VF 32768
#define FA_SMEM 49152

__global__ __launch_bounds__(256)
void flash_mma(const float* __restrict__ Q, const float* __restrict__ K,
               const float* __restrict__ V, float* __restrict__ Out)
{
    extern __shared__ __align__(16) char fsm[];

    const int tid  = threadIdx.x;
    const int wid  = tid >> 5;
    const int lane = tid & 31;
    const int q    = lane & 3;
    const int r0   = lane >> 2;
    const int bh   = blockIdx.y;
    const int qt   = blockIdx.x;

    const float* Qb = Q + (size_t)bh * (T_ * D_) + (size_t)qt * 128 * D_;
    const float* Kb = K + (size_t)bh * (T_ * D_);
    const float* Vb = V + (size_t)bh * (T_ * D_);

    // ---- load Q A-frags (rows wid*16 + r0 / +8), hi/lo split ----
    uint32_t qh[8][4], ql[8][4];
    {
        const int gr = wid * 16 + r0;
#pragma unroll
        for (int ki = 0; ki < 8; ki++) {
            const int c0 = ki * 8 + q;
            float f[4];
            f[0] = Qb[(size_t)gr * D_ + c0];
            f[1] = Qb[(size_t)(gr + 8) * D_ + c0];
            f[2] = Qb[(size_t)gr * D_ + c0 + 4];
            f[3] = Qb[(size_t)(gr + 8) * D_ + c0 + 4];
#pragma unroll
            for (int j = 0; j < 4; j++) {
                qh[ki][j] = tf32_rna_bits(f[j]);
                ql[ki][j] = tf32_rna_bits(f[j] - __uint_as_float(qh[ki][j]));
            }
        }
    }

    float Of[8][4];
#pragma unroll
    for (int nb = 0; nb < 8; nb++)
#pragma unroll
        for (int j = 0; j < 4; j++) Of[nb][j] = 0.0f;
    float m0 = -1e30f, m1 = -1e30f, l0 = 0.0f, l1 = 0.0f;

    for (int kt = 0; kt < T_ / FA_BC; kt++) {
        __syncthreads();   // consumers of previous tile done

        // ---- producer: frag-pack K (hi/lo) and V (single) ----
        const float* Kt = Kb + (size_t)kt * FA_BC * D_;
        const float* Vt = Vb + (size_t)kt * FA_BC * D_;
#pragma unroll
        for (int it = 0; it < 4; it++) {
            const int v  = tid + it * 256;      // 0..1023 float4
            const int n  = v >> 4;              // row 0..63
            const int d0 = (v & 15) * 4;
            const float4 kv = *(const float4*)(Kt + (size_t)n * D_ + d0);
            const float4 vv = *(const float4*)(Vt + (size_t)n * D_ + d0);
            const float kf[4] = {kv.x, kv.y, kv.z, kv.w};
            const float vf4[4] = {vv.x, vv.y, vv.z, vv.w};
            // K: B-operand atom (n-role = kv row n, k-role = d)
            {
                char* kb = fsm + ((n >> 3) * 8 + (d0 >> 3)) * 256
                         + (n & 7) * 32 + ((d0 >> 2) & 1) * 4;
#pragma unroll
                for (int qq = 0; qq < 4; qq++) {
                    const uint32_t hi = tf32_rna_bits(kf[qq]);
                    const uint32_t lo = tf32_rna_bits(kf[qq] - __uint_as_float(hi));
                    *(uint32_t*)(kb + SM_KH + qq * 8) = hi;
                    *(uint32_t*)(kb + SM_KL + qq * 8) = lo;
                }
            }
            // V: B-operand atom (n-role = d, k-role = kv row n)
            {
                char* vb = fsm + SM_VF + ((n >> 2) & 1) * 4 + (n & 3) * 8;
#pragma unroll
                for (int qq = 0; qq < 4; qq++) {
                    const int d = d0 + qq;
                    *(uint32_t*)(vb + ((d >> 3) * 8 + (n >> 3)) * 256
                                 + (d & 7) * 32) = tf32_rna_bits(vf4[qq]);
                }
            }
        }
        __syncthreads();

        // ---- S = Q K^T (3xTF32) ----
        float S[8][4];
#pragma unroll
        for (int nb = 0; nb < 8; nb++)
#pragma unroll
            for (int j = 0; j < 4; j++) S[nb][j] = 0.0f;

#pragma unroll
        for (int ki = 0; ki < 8; ki++) {
#pragma unroll
            for (int nb = 0; nb < 8; nb++) {
                uint32_t kh2[2], kl2[2];
                const char* kb = fsm + ((nb * 8 + ki) * 256) + lane * 8;
                *(uint2*)kh2 = *(const uint2*)(kb + SM_KH);
                *(uint2*)kl2 = *(const uint2*)(kb + SM_KL);
                mma_tf32(S[nb], qh[ki], kh2);
                mma_tf32(S[nb], qh[ki], kl2);
                mma_tf32(S[nb], ql[ki], kh2);
            }
        }

        // ---- online softmax (rows r0, r0+8; quad = lanes sharing row) ----
        float mx0 = -1e30f, mx1 = -1e30f;
#pragma unroll
        for (int nb = 0; nb < 8; nb++) {
#pragma unroll
            for (int j = 0; j < 4; j++) S[nb][j] *= 0.125f;
            mx0 = fmaxf(mx0, fmaxf(S[nb][0], S[nb][1]));
            mx1 = fmaxf(mx1, fmaxf(S[nb][2], S[nb][3]));
        }
        mx0 = fmaxf(mx0, __shfl_xor_sync(0xffffffffu, mx0, 1));
        mx0 = fmaxf(mx0, __shfl_xor_sync(0xffffffffu, mx0, 2));
        mx1 = fmaxf(mx1, __shfl_xor_sync(0xffffffffu, mx1, 1));
        mx1 = fmaxf(mx1, __shfl_xor_sync(0xffffffffu, mx1, 2));

        const float mn0 = fmaxf(m0, mx0);
        const float mn1 = fmaxf(m1, mx1);
        const float a0 = __expf(m0 - mn0);
        const float a1 = __expf(m1 - mn1);
        m0 = mn0; m1 = mn1;

        float rs0 = 0.0f, rs1 = 0.0f;
#pragma unroll
        for (int nb = 0; nb < 8; nb++) {
            S[nb][0] = __expf(S[nb][0] - mn0); rs0 += S[nb][0];
            S[nb][1] = __expf(S[nb][1] - mn0); rs0 += S[nb][1];
            S[nb][2] = __expf(S[nb][2] - mn1); rs1 += S[nb][2];
            S[nb][3] = __expf(S[nb][3] - mn1); rs1 += S[nb][3];
        }
        rs0 += __shfl_xor_sync(0xffffffffu, rs0, 1);
        rs0 += __shfl_xor_sync(0xffffffffu, rs0, 2);
        rs1 += __shfl_xor_sync(0xffffffffu, rs1, 1);
        rs1 += __shfl_xor_sync(0xffffffffu, rs1, 2);
        l0 = l0 * a0 + rs0;
        l1 = l1 * a1 + rs1;
#pragma unroll
        for (int nb = 0; nb < 8; nb++) {
            Of[nb][0] *= a0; Of[nb][1] *= a0;
            Of[nb][2] *= a1; Of[nb][3] *= a1;
        }

        // ---- O += P V (P accum->operand via quad shuffles, hi/lo split) ----
        const int bq = lane & ~3;
        const int s0 = bq | (q >> 1);
        const int s1 = bq | ((q >> 1) + 2);
#pragma unroll
        for (int kc = 0; kc < 8; kc++) {
            float aw[4];
            {
                const float t0 = __shfl_sync(0xffffffffu, S[kc][0], s0);
                const float t1 = __shfl_sync(0xffffffffu, S[kc][1], s0);
                aw[0] = (q & 1) ? t1 : t0;                  // row r0,   col q
                const float u0 = __shfl_sync(0xffffffffu, S[kc][0], s1);
                const float u1 = __shfl_sync(0xffffffffu, S[kc][1], s1);
                aw[2] = (q & 1) ? u1 : u0;                  // row r0,   col q+4
                const float v0 = __shfl_sync(0xffffffffu, S[kc][2], s0);
                const float v1 = __shfl_sync(0xffffffffu, S[kc][3], s0);
                aw[1] = (q & 1) ? v1 : v0;                  // row r0+8, col q
                const float w0 = __shfl_sync(0xffffffffu, S[kc][2], s1);
                const float w1 = __shfl_sync(0xffffffffu, S[kc][3], s1);
                aw[3] = (q & 1) ? w1 : w0;                  // row r0+8, col q+4
            }
            uint32_t ah[4], al[4];
#pragma unroll
            for (int j = 0; j < 4; j++) {
                ah[j] = tf32_rna_bits(aw[j]);
                al[j] = tf32_rna_bits(aw[j] - __uint_as_float(ah[j]));
            }
#pragma unroll
            for (int nb = 0; nb < 8; nb++) {
                uint32_t vf[2];
                *(uint2*)vf = *(const uint2*)(fsm + SM_VF
                              + ((nb * 8 + kc) * 256) + lane * 8);
                mma_tf32(Of[nb], ah, vf);
                mma_tf32(Of[nb], al, vf);
            }
        }
    }

    // ---- epilogue: O /= l, write [B,T,C] ----
    const int b = bh >> 4;
    const int h = bh & 15;
    const int t0r = qt * 128 + wid * 16 + r0;
    const float inv0 = 1.0f / l0;
    const float inv1 = 1.0f / l1;
#pragma unroll
    for (int nb = 0; nb < 8; nb++) {
        const int col = h * 64 + nb * 8 + 2 * q;
        float2 o;
        o.x = Of[nb][0] * inv0; o.y = Of[nb][1] * inv0;
        *(float2*)(&Out[(size_t)(b * T_ + t0r) * C_ + col]) = o;
        o.x = Of[nb][2] * inv1; o.y = Of[nb][3] * inv1;
        *(float2*)(&Out[(size_t)(b * T_ + t0r + 8) * C_ + col]) = o;
    }
}

// ---------------------------------------------------------------------------
extern "C" void kernel_launch(void* const* d_in, const int* in_sizes, int n_in,
                              void* d_out, int out_size)
{
    const float* querys = (const float*)d_in[0];
    const float* keys   = (const float*)d_in[1];
    const float* values = (const float*)d_in[2];
    const float* Wq = (const float*)d_in[3];
    const float* bq = (const float*)d_in[4];
    const float* Wk = (const float*)d_in[5];
    const float* bk = (const float*)d_in[6];
    const float* Wv = (const float*)d_in[7];
    const float* bv = (const float*)d_in[8];
    const float* Wo = (const float*)d_in[9];
    const float* bo = (const float*)d_in[10];

    float *qp, *kp, *vp, *ap;
    cudaGetSymbolAddress((void**)&qp, g_q);
    cudaGetSymbolAddress((void**)&kp, g_k);
    cudaGetSymbolAddress((void**)&vp, g_v);
    cudaGetSymbolAddress((void**)&ap, g_attn);

    cudaFuncSetAttribute(gemm_mma, cudaFuncAttributeMaxDynamicSharedMemorySize,
                         GEMM_SMEM);
    cudaFuncSetAttribute(flash_mma, cudaFuncAttributeMaxDynamicSharedMemorySize,
                         FA_SMEM);

    const dim3 gg(NCOL / 128, M_ROWS / 128);   // (8, 64)

    gemm_mma<<<gg, 256, GEMM_SMEM>>>(querys, Wq, bq, qp, 1);
    gemm_mma<<<gg, 256, GEMM_SMEM>>>(keys,   Wk, bk, kp, 1);
    gemm_mma<<<gg, 256, GEMM_SMEM>>>(values, Wv, bv, vp, 1);

    flash_mma<<<dim3(T_ / 128, B_ * H_), 256, FA_SMEM>>>(qp, kp, vp, ap);

    gemm_mma<<<gg, 256, GEMM_SMEM>>>(ap, Wo, bo, (float*)d_out, 0);
}